// round 1
// baseline (speedup 1.0000x reference)
#include <cuda_runtime.h>
#include <cuda_bf16.h>
#include <cstddef>

#define VOCAB 32000
#define SEQ   2048
#define BATCH 2
#define EMB   1024
#define NH    16
#define HDIM  64
#define FFDIM 4096
#define NLAYERS 4
#define ROWS (BATCH*SEQ)   // 4096

// ---------------- scratch (static device globals; no allocations) ----------
__device__ float g_h   [ (size_t)ROWS*EMB    ];   // 16 MB  residual stream
__device__ float g_qkv [ (size_t)ROWS*3*EMB  ];   // 48 MB
__device__ float g_attn[ (size_t)ROWS*EMB    ];   // 16 MB
__device__ float g_tmp [ (size_t)ROWS*EMB    ];   // 16 MB
__device__ float g_ff  [ (size_t)ROWS*FFDIM  ];   // 64 MB
__device__ int   g_is64;

// ---------------- token dtype detection (int32 vs int64) -------------------
__global__ void detect_dtype_kernel(const void* x) {
    // If tokens are genuinely int64, every value (8 bytes) is in [0, VOCAB).
    // If int32, interpreting pairs as int64 gives lo + (hi<<32) which is huge
    // unless hi==0 (prob ~1/32000 per pair). Checking 8 pairs is conclusive.
    const long long* p = (const long long*)x;
    int ok = 1;
    for (int i = 0; i < 8; i++) {
        long long v = p[i];
        if (v < 0 || v >= VOCAB) ok = 0;
    }
    g_is64 = ok;
}

// ---------------- embedding -----------------------------------------------
__global__ void embed_kernel(const void* __restrict__ x,
                             const float* __restrict__ we,
                             const float* __restrict__ pe,
                             float* __restrict__ out) {
    int row = blockIdx.x;            // b*SEQ + s
    int s   = row & (SEQ - 1);
    int tok;
    if (g_is64) tok = (int)((const long long*)x)[row];
    else        tok = ((const int*)x)[row];
    const float* w = we + (size_t)tok * EMB;
    const float* p = pe + (size_t)s   * EMB;
    float* o = out + (size_t)row * EMB;
    for (int e = threadIdx.x; e < EMB; e += blockDim.x)
        o[e] = w[e] + p[e];
}

// ---------------- SGEMM 128x128x8, 8x8 per thread --------------------------
// C[M,N] = A[M,K] @ B   (B is [K,N] row-major if !BT, else [N,K] row-major)
// All M,N multiples of 128 and K multiples of 8 in this problem.
template<bool BT, bool HASBIAS, bool RELU>
__global__ __launch_bounds__(256)
void sgemm_kernel(const float* __restrict__ A, const float* __restrict__ B,
                  const float* __restrict__ bias, float* __restrict__ C,
                  int M, int N, int K) {
    constexpr int BM = 128, BN = 128, BK = 8;
    __shared__ float As[BK][BM];
    __shared__ float Bs[BK][BN];

    const int tid = threadIdx.x;
    const int tx  = tid & 15;        // 16 thread cols
    const int ty  = tid >> 4;        // 16 thread rows
    const int row0 = blockIdx.y * BM;
    const int col0 = blockIdx.x * BN;

    float acc[8][8];
#pragma unroll
    for (int i = 0; i < 8; i++)
#pragma unroll
        for (int j = 0; j < 8; j++) acc[i][j] = 0.f;

    for (int k0 = 0; k0 < K; k0 += BK) {
        // A tile: 128x8, stored transposed As[k][m]
#pragma unroll
        for (int i = 0; i < 4; i++) {
            int idx = tid + i * 256;
            int m = idx >> 3, k = idx & 7;
            As[k][m] = A[(size_t)(row0 + m) * K + k0 + k];
        }
        // B tile: 8x128 -> Bs[k][n]
        if (!BT) {
#pragma unroll
            for (int i = 0; i < 4; i++) {
                int idx = tid + i * 256;
                int k = idx >> 7, n = idx & 127;
                Bs[k][n] = B[(size_t)(k0 + k) * N + col0 + n];
            }
        } else {
#pragma unroll
            for (int i = 0; i < 4; i++) {
                int idx = tid + i * 256;
                int n = idx >> 3, k = idx & 7;
                Bs[k][n] = B[(size_t)(col0 + n) * K + k0 + k];
            }
        }
        __syncthreads();

#pragma unroll
        for (int kk = 0; kk < BK; kk++) {
            float a[8], b[8];
#pragma unroll
            for (int i = 0; i < 8; i++) a[i] = As[kk][ty * 8 + i];
#pragma unroll
            for (int j = 0; j < 8; j++) b[j] = Bs[kk][tx * 8 + j];
#pragma unroll
            for (int i = 0; i < 8; i++)
#pragma unroll
                for (int j = 0; j < 8; j++)
                    acc[i][j] += a[i] * b[j];
        }
        __syncthreads();
    }

#pragma unroll
    for (int i = 0; i < 8; i++) {
        int r = row0 + ty * 8 + i;
        float* c = C + (size_t)r * N + col0 + tx * 8;
#pragma unroll
        for (int j = 0; j < 8; j++) {
            float v = acc[i][j];
            if (HASBIAS) v += bias[col0 + tx * 8 + j];
            if (RELU)    v = fmaxf(v, 0.f);
            c[j] = v;
        }
    }
}

// ---------------- causal attention: one block per (b, h, q) ----------------
// qkv row layout per token: [H][3][HD] with order (k, q, v)
__global__ __launch_bounds__(128)
void attention_kernel(const float* __restrict__ qkv, float* __restrict__ out) {
    const int q = blockIdx.x, h = blockIdx.y, b = blockIdx.z;
    __shared__ float sq[HDIM];
    __shared__ float sc[SEQ];
    __shared__ float red[128];

    const int t = threadIdx.x;
    const size_t mrow = (size_t)b * SEQ + q;
    const float* base = qkv + mrow * (3 * EMB) + h * (3 * HDIM);

    if (t < HDIM) sq[t] = base[HDIM + t];   // q vector
    __syncthreads();

    const int cnt = q + 1;                   // causal: j in [0, q]
    float mx = -1e30f;
    for (int j = t; j < cnt; j += 128) {
        const float* kp = qkv + ((size_t)b * SEQ + j) * (3 * EMB) + h * (3 * HDIM);
        float d = 0.f;
#pragma unroll
        for (int e = 0; e < HDIM; e++) d += sq[e] * kp[e];
        d *= 0.125f;                         // 1/sqrt(64)
        sc[j] = d;
        mx = fmaxf(mx, d);
    }
    red[t] = mx; __syncthreads();
    for (int o = 64; o > 0; o >>= 1) { if (t < o) red[t] = fmaxf(red[t], red[t + o]); __syncthreads(); }
    mx = red[0]; __syncthreads();

    float sum = 0.f;
    for (int j = t; j < cnt; j += 128) {
        float p = __expf(sc[j] - mx);
        sc[j] = p;
        sum += p;
    }
    red[t] = sum; __syncthreads();
    for (int o = 64; o > 0; o >>= 1) { if (t < o) red[t] += red[t + o]; __syncthreads(); }
    const float inv = 1.f / red[0];
    __syncthreads();

    // weighted V: 128 threads = 2 halves x 64 dims
    const int d    = t & 63;
    const int half = t >> 6;
    const int j0 = half ? (cnt >> 1) : 0;
    const int j1 = half ? cnt        : (cnt >> 1);
    float acc = 0.f;
    for (int j = j0; j < j1; j++) {
        const float* vp = qkv + ((size_t)b * SEQ + j) * (3 * EMB) + h * (3 * HDIM) + 2 * HDIM;
        acc += sc[j] * vp[d];
    }
    red[t] = acc; __syncthreads();
    if (t < 64)
        out[mrow * EMB + h * HDIM + t] = (red[t] + red[t + 64]) * inv;
}

// ---------------- layernorm(x)*g + b, added into residual h ----------------
__global__ __launch_bounds__(256)
void ln_residual_kernel(const float* __restrict__ x, const float* __restrict__ g,
                        const float* __restrict__ bb, float* __restrict__ h) {
    const int row = blockIdx.x;
    const float* xr = x + (size_t)row * EMB;
    float* hr = h + (size_t)row * EMB;
    __shared__ float red[256];
    const int t = threadIdx.x;

    float s = 0.f;
    for (int e = t; e < EMB; e += 256) s += xr[e];
    red[t] = s; __syncthreads();
    for (int o = 128; o > 0; o >>= 1) { if (t < o) red[t] += red[t + o]; __syncthreads(); }
    const float mu = red[0] * (1.f / EMB);
    __syncthreads();

    float v = 0.f;
    for (int e = t; e < EMB; e += 256) { float d = xr[e] - mu; v += d * d; }
    red[t] = v; __syncthreads();
    for (int o = 128; o > 0; o >>= 1) { if (t < o) red[t] += red[t + o]; __syncthreads(); }
    const float rstd = rsqrtf(red[0] * (1.f / EMB) + 1e-6f);
    __syncthreads();

    for (int e = t; e < EMB; e += 256)
        hr[e] += (xr[e] - mu) * rstd * g[e] + bb[e];
}

// ---------------- launch orchestration -------------------------------------
extern "C" void kernel_launch(void* const* d_in, const int* in_sizes, int n_in,
                              void* d_out, int out_size) {
    const void*  x    = d_in[0];
    const float* we   = (const float*)d_in[1];
    const float* pe   = (const float*)d_in[2];
    const float* KQV  = (const float*)d_in[3];
    const float* WO   = (const float*)d_in[4];
    const float* Wup  = (const float*)d_in[5];
    const float* bup  = (const float*)d_in[6];
    const float* Wdn  = (const float*)d_in[7];
    const float* bdn  = (const float*)d_in[8];
    const float* g1   = (const float*)d_in[9];
    const float* b1   = (const float*)d_in[10];
    const float* g2   = (const float*)d_in[11];
    const float* b2   = (const float*)d_in[12];
    const float* ub   = (const float*)d_in[13];
    float* out = (float*)d_out;

    float *h, *qkv, *attn, *tmp, *ff;
    cudaGetSymbolAddress((void**)&h,    g_h);
    cudaGetSymbolAddress((void**)&qkv,  g_qkv);
    cudaGetSymbolAddress((void**)&attn, g_attn);
    cudaGetSymbolAddress((void**)&tmp,  g_tmp);
    cudaGetSymbolAddress((void**)&ff,   g_ff);

    detect_dtype_kernel<<<1, 1>>>(x);
    embed_kernel<<<ROWS, 256>>>(x, we, pe, h);

    const dim3 blk(256);
    for (int l = 0; l < NLAYERS; l++) {
        const float* kqv_l = KQV + (size_t)l * EMB * 3 * EMB;
        const float* wo_l  = WO  + (size_t)l * EMB * EMB;
        const float* wu_l  = Wup + (size_t)l * EMB * FFDIM;
        const float* bu_l  = bup + (size_t)l * FFDIM;
        const float* wd_l  = Wdn + (size_t)l * FFDIM * EMB;
        const float* bd_l  = bdn + (size_t)l * EMB;

        // qkv = h @ KQV   [4096 x 3072]
        sgemm_kernel<false, false, false><<<dim3(3 * EMB / 128, ROWS / 128), blk>>>(
            h, kqv_l, nullptr, qkv, ROWS, 3 * EMB, EMB);

        // causal attention
        attention_kernel<<<dim3(SEQ, NH, BATCH), 128>>>(qkv, attn);

        // proj = attn @ WO  [4096 x 1024]
        sgemm_kernel<false, false, false><<<dim3(EMB / 128, ROWS / 128), blk>>>(
            attn, wo_l, nullptr, tmp, ROWS, EMB, EMB);

        // h = LN(proj)*g1+b1 + h
        ln_residual_kernel<<<ROWS, 256>>>(tmp, g1 + (size_t)l * EMB, b1 + (size_t)l * EMB, h);

        // ff = relu(h @ Wup + bup)  [4096 x 4096]
        sgemm_kernel<false, true, true><<<dim3(FFDIM / 128, ROWS / 128), blk>>>(
            h, wu_l, bu_l, ff, ROWS, FFDIM, EMB);

        // tmp = ff @ Wdn + bdn  [4096 x 1024]
        sgemm_kernel<false, true, false><<<dim3(EMB / 128, ROWS / 128), blk>>>(
            ff, wd_l, bd_l, tmp, ROWS, EMB, FFDIM);

        // h = LN(tmp)*g2+b2 + h
        ln_residual_kernel<<<ROWS, 256>>>(tmp, g2 + (size_t)l * EMB, b2 + (size_t)l * EMB, h);
    }

    // logits = h @ we^T + ub   [4096 x 32000], NT
    sgemm_kernel<true, true, false><<<dim3(VOCAB / 128, ROWS / 128), blk>>>(
        h, we, ub, out, ROWS, VOCAB, EMB);
}

// round 4
// speedup vs baseline: 1.1962x; 1.1962x over previous
#include <cuda_runtime.h>
#include <cuda_bf16.h>
#include <cstdint>
#include <cstddef>

typedef __nv_bfloat16 bf16;

#define VOCAB 32000
#define SEQ   2048
#define BATCH 2
#define EMB   1024
#define NH    16
#define HDIM  64
#define FFDIM 4096
#define NLAYERS 4
#define ROWS (BATCH*SEQ)   // 4096

// ---------------- scratch (static device globals; no allocations) ----------
__device__ float g_h   [ (size_t)ROWS*EMB    ];
__device__ float g_qkv [ (size_t)ROWS*3*EMB  ];
__device__ float g_attn[ (size_t)ROWS*EMB    ];
__device__ float g_tmp [ (size_t)ROWS*EMB    ];
__device__ float g_ff  [ (size_t)ROWS*FFDIM  ];
__device__ int   g_is64;

// bf16 split buffers (hi/lo). Weights stored transposed: [N][K].
__device__ __align__(256) bf16 g_wkqv_h[(size_t)NLAYERS*3*EMB*EMB];
__device__ __align__(256) bf16 g_wkqv_l[(size_t)NLAYERS*3*EMB*EMB];
__device__ __align__(256) bf16 g_wwo_h [(size_t)NLAYERS*EMB*EMB];
__device__ __align__(256) bf16 g_wwo_l [(size_t)NLAYERS*EMB*EMB];
__device__ __align__(256) bf16 g_wup_h [(size_t)NLAYERS*FFDIM*EMB];
__device__ __align__(256) bf16 g_wup_l [(size_t)NLAYERS*FFDIM*EMB];
__device__ __align__(256) bf16 g_wdn_h [(size_t)NLAYERS*EMB*FFDIM];
__device__ __align__(256) bf16 g_wdn_l [(size_t)NLAYERS*EMB*FFDIM];
__device__ __align__(256) bf16 g_we_h  [(size_t)VOCAB*EMB];
__device__ __align__(256) bf16 g_we_l  [(size_t)VOCAB*EMB];
__device__ __align__(256) bf16 g_a_h   [(size_t)ROWS*FFDIM];
__device__ __align__(256) bf16 g_a_l   [(size_t)ROWS*FFDIM];

// ---------------- PTX helpers (baseline ISA only; no sm_103a features) -----
__device__ __forceinline__ uint32_t smem_u32(const void* p) {
    uint32_t a;
    asm("{ .reg .u64 t; cvta.to.shared.u64 t, %1; cvt.u32.u64 %0, t; }" : "=r"(a) : "l"(p));
    return a;
}
__device__ __forceinline__ void cp16(uint32_t saddr, const void* g) {
    asm volatile("cp.async.cg.shared.global [%0], [%1], 16;" :: "r"(saddr), "l"(g));
}
__device__ __forceinline__ void ldsm4(uint32_t* r, uint32_t addr) {
    asm volatile("ldmatrix.sync.aligned.m8n8.x4.shared.b16 {%0,%1,%2,%3}, [%4];"
        : "=r"(r[0]), "=r"(r[1]), "=r"(r[2]), "=r"(r[3]) : "r"(addr));
}
__device__ __forceinline__ void mma16816(float* c, const uint32_t* a, const uint32_t* b) {
    asm volatile("mma.sync.aligned.m16n8k16.row.col.f32.bf16.bf16.f32 "
        "{%0,%1,%2,%3}, {%4,%5,%6,%7}, {%8,%9}, {%0,%1,%2,%3};"
        : "+f"(c[0]), "+f"(c[1]), "+f"(c[2]), "+f"(c[3])
        : "r"(a[0]), "r"(a[1]), "r"(a[2]), "r"(a[3]), "r"(b[0]), "r"(b[1]));
}

// ---------------- token dtype detection ------------------------------------
__global__ void detect_dtype_kernel(const void* x) {
    const long long* p = (const long long*)x;
    int ok = 1;
    for (int i = 0; i < 8; i++) {
        long long v = p[i];
        if (v < 0 || v >= VOCAB) ok = 0;
    }
    g_is64 = ok;
}

// ---------------- embedding -------------------------------------------------
__global__ void embed_kernel(const void* __restrict__ x,
                             const float* __restrict__ we,
                             const float* __restrict__ pe,
                             float* __restrict__ out) {
    int row = blockIdx.x;
    int s   = row & (SEQ - 1);
    int tok;
    if (g_is64) tok = (int)((const long long*)x)[row];
    else        tok = ((const int*)x)[row];
    const float* w = we + (size_t)tok * EMB;
    const float* p = pe + (size_t)s   * EMB;
    float* o = out + (size_t)row * EMB;
    for (int e = threadIdx.x; e < EMB; e += blockDim.x)
        o[e] = w[e] + p[e];
}

// ---------------- fp32 -> (hi, lo) bf16 split, straight ---------------------
__global__ __launch_bounds__(256)
void split_kernel(const float* __restrict__ in, bf16* __restrict__ hi,
                  bf16* __restrict__ lo, int n4) {
    int i = blockIdx.x * 256 + threadIdx.x;
    if (i >= n4) return;
    float4 v = ((const float4*)in)[i];
    bf16 h0 = __float2bfloat16(v.x), h1 = __float2bfloat16(v.y);
    bf16 h2 = __float2bfloat16(v.z), h3 = __float2bfloat16(v.w);
    bf16 l0 = __float2bfloat16(v.x - __bfloat162float(h0));
    bf16 l1 = __float2bfloat16(v.y - __bfloat162float(h1));
    bf16 l2 = __float2bfloat16(v.z - __bfloat162float(h2));
    bf16 l3 = __float2bfloat16(v.w - __bfloat162float(h3));
    ((__nv_bfloat162*)hi)[2*i]   = __halves2bfloat162(h0, h1);
    ((__nv_bfloat162*)hi)[2*i+1] = __halves2bfloat162(h2, h3);
    ((__nv_bfloat162*)lo)[2*i]   = __halves2bfloat162(l0, l1);
    ((__nv_bfloat162*)lo)[2*i+1] = __halves2bfloat162(l2, l3);
}

// ---------------- fp32 [K,N] -> transposed bf16 split [N,K] -----------------
__global__ __launch_bounds__(256)
void splitT_kernel(const float* __restrict__ W, bf16* __restrict__ hiT,
                   bf16* __restrict__ loT, int K, int N) {
    __shared__ float ts[32][33];
    int tx = threadIdx.x, ty = threadIdx.y;      // 32 x 8
    int n0 = blockIdx.x * 32, k0 = blockIdx.y * 32;
#pragma unroll
    for (int j = 0; j < 32; j += 8)
        ts[ty + j][tx] = W[(size_t)(k0 + ty + j) * N + n0 + tx];
    __syncthreads();
#pragma unroll
    for (int j = 0; j < 32; j += 8) {
        float v = ts[tx][ty + j];
        bf16 h = __float2bfloat16(v);
        size_t o = (size_t)(n0 + ty + j) * K + k0 + tx;
        hiT[o] = h;
        loT[o] = __float2bfloat16(v - __bfloat162float(h));
    }
}

// ---------------- HMMA bf16x3 GEMM: C[M,N] = A[M,K] @ B[N,K]^T --------------
// CTA tile 256x128, 8 warps (4x2), warp tile 64x64, BK=32, cp.async dbl-buf.
// smem pitch 80B/row (5 x 16B): conflict-free LDSM phases, aligned cp.async.
#define BM 256
#define BN 128
#define BKC 32
#define SPITCH 80                      // bytes per smem row (32 bf16 + pad)
#define A_BYTES (BM * SPITCH)          // 20480
#define B_BYTES (BN * SPITCH)          // 10240
#define BUF_BYTES (2 * A_BYTES + 2 * B_BYTES)   // 61440
#define SMEM_TOT (2 * BUF_BYTES)       // 122880

template<bool HB, bool DORELU>
__global__ __launch_bounds__(256, 1)
void tgemm_kernel(const bf16* __restrict__ Ah, const bf16* __restrict__ Al,
                  const bf16* __restrict__ Bh, const bf16* __restrict__ Bl,
                  const float* __restrict__ bias, float* __restrict__ C,
                  int N, int K) {
    extern __shared__ __align__(1024) char ds[];
    const uint32_t sb = smem_u32(ds);
    const int t = threadIdx.x;
    const int w = t >> 5, lane = t & 31;
    const int row0 = blockIdx.x * BM, col0 = blockIdx.y * BN;
    const int warp_m = (w >> 1) * 64, warp_n = (w & 1) * 64;

    // offsets within a buffer: Ah=0, Al=A_BYTES, Bh=2*A_BYTES, Bl=2*A_BYTES+B_BYTES
    auto load_chunk = [&](int k0, int b) {
        const uint32_t base = sb + (uint32_t)b * BUF_BYTES;
#pragma unroll
        for (int i = 0; i < 4; i++) {
            int idx = t + i * 256;
            int r = idx >> 2, cg = idx & 3;
            uint32_t so = base + (uint32_t)(r * SPITCH + cg * 16);
            size_t go = (size_t)(row0 + r) * K + k0 + cg * 8;
            cp16(so,            Ah + go);
            cp16(so + A_BYTES,  Al + go);
        }
#pragma unroll
        for (int i = 0; i < 2; i++) {
            int idx = t + i * 256;
            int r = idx >> 2, cg = idx & 3;
            uint32_t so = base + 2 * A_BYTES + (uint32_t)(r * SPITCH + cg * 16);
            size_t go = (size_t)(col0 + r) * K + k0 + cg * 8;
            cp16(so,            Bh + go);
            cp16(so + B_BYTES,  Bl + go);
        }
        asm volatile("cp.async.commit_group;" ::: "memory");
    };

    float acc[4][8][4];
#pragma unroll
    for (int mi = 0; mi < 4; mi++)
#pragma unroll
        for (int nj = 0; nj < 8; nj++)
#pragma unroll
            for (int c = 0; c < 4; c++) acc[mi][nj][c] = 0.f;

    const int NC = K >> 5;
    load_chunk(0, 0);

    const int rsel = lane & 15;        // ldmatrix row within 16
    const int csel = lane >> 4;        // 0/1: which 8-col half (16B)

    for (int i = 0; i < NC; i++) {
        if (i + 1 < NC) {
            load_chunk((i + 1) << 5, (i + 1) & 1);
            asm volatile("cp.async.wait_group 1;" ::: "memory");
        } else {
            asm volatile("cp.async.wait_group 0;" ::: "memory");
        }
        __syncthreads();

        const uint32_t base = sb + (uint32_t)(i & 1) * BUF_BYTES;
#pragma unroll
        for (int ks = 0; ks < 2; ks++) {
            const uint32_t koff = (uint32_t)(ks * 32 + csel * 16);
            uint32_t ah[4][4], al[4][4];
#pragma unroll
            for (int mi = 0; mi < 4; mi++) {
                uint32_t ra = base + (uint32_t)((warp_m + mi * 16 + rsel) * SPITCH) + koff;
                ldsm4(ah[mi], ra);
                ldsm4(al[mi], ra + A_BYTES);
            }
            uint32_t bh[8][2], bl[8][2];
#pragma unroll
            for (int nj = 0; nj < 4; nj++) {
                uint32_t rb = base + 2 * A_BYTES +
                              (uint32_t)((warp_n + nj * 16 + rsel) * SPITCH) + koff;
                uint32_t q[4];
                ldsm4(q, rb);
                bh[2*nj][0] = q[0]; bh[2*nj][1] = q[2];
                bh[2*nj+1][0] = q[1]; bh[2*nj+1][1] = q[3];
                ldsm4(q, rb + B_BYTES);
                bl[2*nj][0] = q[0]; bl[2*nj][1] = q[2];
                bl[2*nj+1][0] = q[1]; bl[2*nj+1][1] = q[3];
            }
#pragma unroll
            for (int mi = 0; mi < 4; mi++)
#pragma unroll
                for (int nj = 0; nj < 8; nj++) {
                    mma16816(acc[mi][nj], ah[mi], bh[nj]);
                    mma16816(acc[mi][nj], ah[mi], bl[nj]);
                    mma16816(acc[mi][nj], al[mi], bh[nj]);
                }
        }
        __syncthreads();
    }

    // epilogue: direct stores, float2 per frag-row (full 32B sectors)
    const int r_in = lane >> 2;
    const int c_in = (lane & 3) * 2;
#pragma unroll
    for (int nj = 0; nj < 8; nj++) {
        const int col = col0 + warp_n + nj * 8 + c_in;
        float b0 = 0.f, b1 = 0.f;
        if (HB) { b0 = bias[col]; b1 = bias[col + 1]; }
#pragma unroll
        for (int mi = 0; mi < 4; mi++) {
            const int row = row0 + warp_m + mi * 16 + r_in;
            float v0 = acc[mi][nj][0] + b0, v1 = acc[mi][nj][1] + b1;
            float v2 = acc[mi][nj][2] + b0, v3 = acc[mi][nj][3] + b1;
            if (DORELU) {
                v0 = fmaxf(v0, 0.f); v1 = fmaxf(v1, 0.f);
                v2 = fmaxf(v2, 0.f); v3 = fmaxf(v3, 0.f);
            }
            *(float2*)&C[(size_t)row * N + col]       = make_float2(v0, v1);
            *(float2*)&C[(size_t)(row + 8) * N + col] = make_float2(v2, v3);
        }
    }
}

// ---------------- causal attention (memory-bound, ~15us/launch) -------------
__global__ __launch_bounds__(128)
void attention_kernel(const float* __restrict__ qkv, float* __restrict__ out) {
    const int q = blockIdx.x, h = blockIdx.y, b = blockIdx.z;
    __shared__ float sq[HDIM];
    __shared__ float sc[SEQ];
    __shared__ float red[128];

    const int t = threadIdx.x;
    const size_t mrow = (size_t)b * SEQ + q;
    const float* base = qkv + mrow * (3 * EMB) + h * (3 * HDIM);

    if (t < HDIM) sq[t] = base[HDIM + t];
    __syncthreads();

    const int cnt = q + 1;
    float mx = -1e30f;
    for (int j = t; j < cnt; j += 128) {
        const float* kp = qkv + ((size_t)b * SEQ + j) * (3 * EMB) + h * (3 * HDIM);
        float d = 0.f;
#pragma unroll
        for (int e = 0; e < HDIM; e++) d += sq[e] * kp[e];
        d *= 0.125f;
        sc[j] = d;
        mx = fmaxf(mx, d);
    }
    red[t] = mx; __syncthreads();
    for (int o = 64; o > 0; o >>= 1) { if (t < o) red[t] = fmaxf(red[t], red[t + o]); __syncthreads(); }
    mx = red[0]; __syncthreads();

    float sum = 0.f;
    for (int j = t; j < cnt; j += 128) {
        float p = __expf(sc[j] - mx);
        sc[j] = p;
        sum += p;
    }
    red[t] = sum; __syncthreads();
    for (int o = 64; o > 0; o >>= 1) { if (t < o) red[t] += red[t + o]; __syncthreads(); }
    const float inv = 1.f / red[0];
    __syncthreads();

    const int d    = t & 63;
    const int half = t >> 6;
    const int j0 = half ? (cnt >> 1) : 0;
    const int j1 = half ? cnt        : (cnt >> 1);
    float acc = 0.f;
    for (int j = j0; j < j1; j++) {
        const float* vp = qkv + ((size_t)b * SEQ + j) * (3 * EMB) + h * (3 * HDIM) + 2 * HDIM;
        acc += sc[j] * vp[d];
    }
    red[t] = acc; __syncthreads();
    if (t < 64)
        out[mrow * EMB + h * HDIM + t] = (red[t] + red[t + 64]) * inv;
}

// ---------------- layernorm(x)*g + b, added into residual h -----------------
__global__ __launch_bounds__(256)
void ln_residual_kernel(const float* __restrict__ x, const float* __restrict__ g,
                        const float* __restrict__ bb, float* __restrict__ h) {
    const int row = blockIdx.x;
    const float* xr = x + (size_t)row * EMB;
    float* hr = h + (size_t)row * EMB;
    __shared__ float red[256];
    const int t = threadIdx.x;

    float s = 0.f;
    for (int e = t; e < EMB; e += 256) s += xr[e];
    red[t] = s; __syncthreads();
    for (int o = 128; o > 0; o >>= 1) { if (t < o) red[t] += red[t + o]; __syncthreads(); }
    const float mu = red[0] * (1.f / EMB);
    __syncthreads();

    float v = 0.f;
    for (int e = t; e < EMB; e += 256) { float d = xr[e] - mu; v += d * d; }
    red[t] = v; __syncthreads();
    for (int o = 128; o > 0; o >>= 1) { if (t < o) red[t] += red[t + o]; __syncthreads(); }
    const float rstd = rsqrtf(red[0] * (1.f / EMB) + 1e-6f);
    __syncthreads();

    for (int e = t; e < EMB; e += 256)
        hr[e] += (xr[e] - mu) * rstd * g[e] + bb[e];
}

// ---------------- launch orchestration --------------------------------------
static void split_act(const float* src, bf16* hi, bf16* lo, size_t n) {
    int n4 = (int)(n / 4);
    split_kernel<<<(n4 + 255) / 256, 256>>>(src, hi, lo, n4);
}

extern "C" void kernel_launch(void* const* d_in, const int* in_sizes, int n_in,
                              void* d_out, int out_size) {
    const void*  x    = d_in[0];
    const float* we   = (const float*)d_in[1];
    const float* pe   = (const float*)d_in[2];
    const float* KQV  = (const float*)d_in[3];
    const float* WO   = (const float*)d_in[4];
    const float* Wup  = (const float*)d_in[5];
    const float* bup  = (const float*)d_in[6];
    const float* Wdn  = (const float*)d_in[7];
    const float* bdn  = (const float*)d_in[8];
    const float* g1   = (const float*)d_in[9];
    const float* b1   = (const float*)d_in[10];
    const float* g2   = (const float*)d_in[11];
    const float* b2   = (const float*)d_in[12];
    const float* ub   = (const float*)d_in[13];
    float* out = (float*)d_out;

    float *h, *qkv, *attn, *tmp, *ff;
    cudaGetSymbolAddress((void**)&h,    g_h);
    cudaGetSymbolAddress((void**)&qkv,  g_qkv);
    cudaGetSymbolAddress((void**)&attn, g_attn);
    cudaGetSymbolAddress((void**)&tmp,  g_tmp);
    cudaGetSymbolAddress((void**)&ff,   g_ff);

    bf16 *wkqv_h, *wkqv_l, *wwo_h, *wwo_l, *wup_h, *wup_l, *wdn_h, *wdn_l;
    bf16 *we_h, *we_l, *a_h, *a_l;
    cudaGetSymbolAddress((void**)&wkqv_h, g_wkqv_h);
    cudaGetSymbolAddress((void**)&wkqv_l, g_wkqv_l);
    cudaGetSymbolAddress((void**)&wwo_h,  g_wwo_h);
    cudaGetSymbolAddress((void**)&wwo_l,  g_wwo_l);
    cudaGetSymbolAddress((void**)&wup_h,  g_wup_h);
    cudaGetSymbolAddress((void**)&wup_l,  g_wup_l);
    cudaGetSymbolAddress((void**)&wdn_h,  g_wdn_h);
    cudaGetSymbolAddress((void**)&wdn_l,  g_wdn_l);
    cudaGetSymbolAddress((void**)&we_h,   g_we_h);
    cudaGetSymbolAddress((void**)&we_l,   g_we_l);
    cudaGetSymbolAddress((void**)&a_h,    g_a_h);
    cudaGetSymbolAddress((void**)&a_l,    g_a_l);

    cudaFuncSetAttribute(tgemm_kernel<false,false>, cudaFuncAttributeMaxDynamicSharedMemorySize, SMEM_TOT);
    cudaFuncSetAttribute(tgemm_kernel<true,true>,   cudaFuncAttributeMaxDynamicSharedMemorySize, SMEM_TOT);
    cudaFuncSetAttribute(tgemm_kernel<true,false>,  cudaFuncAttributeMaxDynamicSharedMemorySize, SMEM_TOT);

    // --- weight conversions (deterministic, every call) ---
    {
        dim3 tblk(32, 8);
        for (int l = 0; l < NLAYERS; l++) {
            splitT_kernel<<<dim3(3*EMB/32, EMB/32), tblk>>>(
                KQV + (size_t)l*EMB*3*EMB, wkqv_h + (size_t)l*3*EMB*EMB,
                wkqv_l + (size_t)l*3*EMB*EMB, EMB, 3*EMB);
            splitT_kernel<<<dim3(EMB/32, EMB/32), tblk>>>(
                WO + (size_t)l*EMB*EMB, wwo_h + (size_t)l*EMB*EMB,
                wwo_l + (size_t)l*EMB*EMB, EMB, EMB);
            splitT_kernel<<<dim3(FFDIM/32, EMB/32), tblk>>>(
                Wup + (size_t)l*EMB*FFDIM, wup_h + (size_t)l*FFDIM*EMB,
                wup_l + (size_t)l*FFDIM*EMB, EMB, FFDIM);
            splitT_kernel<<<dim3(EMB/32, FFDIM/32), tblk>>>(
                Wdn + (size_t)l*FFDIM*EMB, wdn_h + (size_t)l*EMB*FFDIM,
                wdn_l + (size_t)l*EMB*FFDIM, FFDIM, EMB);
        }
        split_act(we, we_h, we_l, (size_t)VOCAB*EMB);   // already [N,K]
    }

    detect_dtype_kernel<<<1, 1>>>(x);
    embed_kernel<<<ROWS, 256>>>(x, we, pe, h);

    for (int l = 0; l < NLAYERS; l++) {
        const float* bu_l = bup + (size_t)l * FFDIM;
        const float* bd_l = bdn + (size_t)l * EMB;

        // qkv = h @ KQV   [4096 x 3072], K=1024
        split_act(h, a_h, a_l, (size_t)ROWS*EMB);
        tgemm_kernel<false,false><<<dim3(ROWS/BM, 3*EMB/BN), 256, SMEM_TOT>>>(
            a_h, a_l, wkqv_h + (size_t)l*3*EMB*EMB, wkqv_l + (size_t)l*3*EMB*EMB,
            nullptr, qkv, 3*EMB, EMB);

        attention_kernel<<<dim3(SEQ, NH, BATCH), 128>>>(qkv, attn);

        // tmp = attn @ WO  [4096 x 1024], K=1024
        split_act(attn, a_h, a_l, (size_t)ROWS*EMB);
        tgemm_kernel<false,false><<<dim3(ROWS/BM, EMB/BN), 256, SMEM_TOT>>>(
            a_h, a_l, wwo_h + (size_t)l*EMB*EMB, wwo_l + (size_t)l*EMB*EMB,
            nullptr, tmp, EMB, EMB);

        ln_residual_kernel<<<ROWS, 256>>>(tmp, g1 + (size_t)l*EMB, b1 + (size_t)l*EMB, h);

        // ff = relu(h @ Wup + bup)  [4096 x 4096], K=1024
        split_act(h, a_h, a_l, (size_t)ROWS*EMB);
        tgemm_kernel<true,true><<<dim3(ROWS/BM, FFDIM/BN), 256, SMEM_TOT>>>(
            a_h, a_l, wup_h + (size_t)l*FFDIM*EMB, wup_l + (size_t)l*FFDIM*EMB,
            bu_l, ff, FFDIM, EMB);

        // tmp = ff @ Wdn + bdn  [4096 x 1024], K=4096
        split_act(ff, a_h, a_l, (size_t)ROWS*FFDIM);
        tgemm_kernel<true,false><<<dim3(ROWS/BM, EMB/BN), 256, SMEM_TOT>>>(
            a_h, a_l, wdn_h + (size_t)l*EMB*FFDIM, wdn_l + (size_t)l*EMB*FFDIM,
            bd_l, tmp, EMB, FFDIM);

        ln_residual_kernel<<<ROWS, 256>>>(tmp, g2 + (size_t)l*EMB, b2 + (size_t)l*EMB, h);
    }

    // logits = h @ we^T + ub   [4096 x 32000], K=1024
    split_act(h, a_h, a_l, (size_t)ROWS*EMB);
    tgemm_kernel<true,false><<<dim3(ROWS/BM, VOCAB/BN), 256, SMEM_TOT>>>(
        a_h, a_l, we_h, we_l, ub, out, VOCAB, EMB);
}